// round 15
// baseline (speedup 1.0000x reference)
#include <cuda_runtime.h>

// Neural 2D min-sum LDPC decoder, (3,6)-regular layered graph.
// One CTA per codeword (TPB=1024, 1 CTA/SM). SPLIT message layout:
//   A [l*NV + i] : v2c in CHECK order (i = position in layer l; check c owns
//                  i = 2c, 2c+1)  -> check-phase loads are coalesced float2.
//   Bm[l*NV + v] : c2v in VARIABLE order -> var-phase loads are coalesced.
// ALL random traffic is stores (no return dependency): check scatters c2v via
// pk (check->var), var scatters v2c via ip (var->position, inverse permutation
// built once per CTA by smem scatter). Randomness total is conserved (2 random
// ops/edge/iter, the floor) but no load ever stalls on a random access.

#define NV 8192
#define MC 4096
#define NL 3
#define TPB 1024
#define VPT (NV / TPB)    // 8 strided variables per thread
#define CPT (MC / TPB)    // 4 checks per thread (strided)
#define SMEM_BYTES (2 * NL * NV * 4)   // A (96KB) + Bm (96KB) = 192KB

// Multiset 2-min min-sum core on sign-magnitude bits; exactly reproduces the
// reference min1/min2/argmin + sign-product semantics (incl. ties and zeros).
// (validated rel_err==0.0 in R5-R14 benches; order-independent)
__device__ __forceinline__ void minsum6(const unsigned u[6], float bt, unsigned res[6])
{
    unsigned a0 = u[0] & 0x7fffffffu, a1 = u[1] & 0x7fffffffu;
    unsigned a2 = u[2] & 0x7fffffffu, a3 = u[3] & 0x7fffffffu;
    unsigned a4 = u[4] & 0x7fffffffu, a5 = u[5] & 0x7fffffffu;
    unsigned xs = (u[0] ^ u[1]) ^ (u[2] ^ u[3]) ^ (u[4] ^ u[5]);

    unsigned lo01 = min(a0, a1), hi01 = max(a0, a1);
    unsigned lo23 = min(a2, a3), hi23 = max(a2, a3);
    unsigned lo45 = min(a4, a5), hi45 = max(a4, a5);
    unsigned m1a  = min(lo01, lo23);
    unsigned m2a  = min(max(lo01, lo23), min(hi01, hi23));
    unsigned m1   = min(m1a, lo45);
    unsigned m2   = min(max(m1a, lo45), min(m2a, hi45));
    m2 = (m1 == 0u) ? 0u : m2;   // exact zero => sign product 0 => all c2v = 0

    unsigned b1 = __float_as_uint(bt * __uint_as_float(m1));
    unsigned b2 = __float_as_uint(bt * __uint_as_float(m2));

    unsigned as[6] = {a0, a1, a2, a3, a4, a5};
#pragma unroll
    for (int p = 0; p < 6; p++) {
        unsigned mag = (as[p] == m1) ? b2 : b1;          // ties => b1==b2
        res[p] = mag ^ ((xs ^ u[p]) & 0x80000000u);
    }
}

__global__ __launch_bounds__(TPB, 1)
void bp_kernel(const float* __restrict__ llr,
               const int*   __restrict__ edge_v,
               const float* __restrict__ beta,
               const float* __restrict__ alpha,
               float* __restrict__ out_f,
               int*   __restrict__ out_i,
               int B, int T, int mode)
{
    extern __shared__ float smem[];
    float* A  = smem;                 // [NL*NV] v2c, check order
    float* Bm = smem + NL * NV;       // [NL*NV] c2v, variable order

    const int tid = threadIdx.x;

    // ---- check->var table pk (for random c2v stores), register-resident ----
    unsigned pk[CPT][NL];
#pragma unroll
    for (int k = 0; k < CPT; k++) {
        int c = tid + k * TPB;
#pragma unroll
        for (int l = 0; l < NL; l++) {
            unsigned v0 = (unsigned)edge_v[l * NV + 2 * c];
            unsigned v1 = (unsigned)edge_v[l * NV + 2 * c + 1];
            pk[k][l] = v0 | (v1 << 16);
        }
    }

    // ---- inverse permutation ip (var -> position), one-time smem scatter ----
    // Scratch = Bm planes (overwritten by first check phase before any read).
    int* iscr = (int*)Bm;
#pragma unroll
    for (int k = 0; k < VPT; k++) {
        int i = tid + k * TPB;
#pragma unroll
        for (int l = 0; l < NL; l++)
            iscr[l * NV + edge_v[l * NV + i]] = i;     // random STS (one-time)
    }
    __syncthreads();
    unsigned ipk[VPT / 2][NL];   // packed: positions of vars 2g, 2g+1 per layer
#pragma unroll
    for (int g = 0; g < VPT / 2; g++) {
        int va = tid + (2 * g) * TPB;
        int vb = tid + (2 * g + 1) * TPB;
#pragma unroll
        for (int l = 0; l < NL; l++) {
            unsigned ia = (unsigned)iscr[l * NV + va];  // coalesced LDS
            unsigned ib = (unsigned)iscr[l * NV + vb];
            ipk[g][l] = ia | (ib << 16);
        }
    }
    __syncthreads();

    for (int cw = blockIdx.x; cw < B; cw += gridDim.x) {
        // Channel LLRs: strided, coalesced, register-resident.
        float llrv[VPT];
#pragma unroll
        for (int k = 0; k < VPT; k++)
            llrv[k] = llr[(size_t)cw * NV + tid + k * TPB];

        // v2c init = llr at each edge, scattered into check order.
#pragma unroll
        for (int g = 0; g < VPT / 2; g++)
#pragma unroll
            for (int l = 0; l < NL; l++) {
                A[l * NV + (int)(ipk[g][l] & 0xFFFFu)] = llrv[2 * g];
                A[l * NV + (int)(ipk[g][l] >> 16)]     = llrv[2 * g + 1];
            }
        __syncthreads();

        for (int t = 0; t < T; t++) {
            float bt = __ldg(beta + t);
            float at = __ldg(alpha + t);

            // ---- check phase: coalesced float2 loads, random c2v stores ----
#pragma unroll
            for (int k = 0; k < CPT; k++) {
                int pos = 2 * (tid + k * TPB);      // even, float2-aligned
                float2 w0 = *(float2*)(A + pos);
                float2 w1 = *(float2*)(A + NV + pos);
                float2 w2 = *(float2*)(A + 2 * NV + pos);
                unsigned u[6] = {
                    __float_as_uint(w0.x), __float_as_uint(w0.y),
                    __float_as_uint(w1.x), __float_as_uint(w1.y),
                    __float_as_uint(w2.x), __float_as_uint(w2.y)
                };
                unsigned r[6];
                minsum6(u, bt, r);
#pragma unroll
                for (int l = 0; l < NL; l++) {
                    Bm[l * NV + (int)(pk[k][l] & 0xFFFFu)] = __uint_as_float(r[2 * l]);
                    Bm[l * NV + (int)(pk[k][l] >> 16)]     = __uint_as_float(r[2 * l + 1]);
                }
            }
            __syncthreads();

            // ---- var phase: coalesced c2v loads, random v2c stores ----
            if (t + 1 < T) {
#pragma unroll
                for (int g = 0; g < VPT / 2; g++) {
                    int va = tid + (2 * g) * TPB;
                    int vb = tid + (2 * g + 1) * TPB;
                    float a0 = Bm[va], a1 = Bm[NV + va], a2 = Bm[2 * NV + va];
                    float b0 = Bm[vb], b1 = Bm[NV + vb], b2 = Bm[2 * NV + vb];
                    float sa = a0 + a1 + a2, ba = llrv[2 * g];
                    float sb = b0 + b1 + b2, bb = llrv[2 * g + 1];
                    float na0 = ba + at * (sa - a0), na1 = ba + at * (sa - a1), na2 = ba + at * (sa - a2);
                    float nb0 = bb + at * (sb - b0), nb1 = bb + at * (sb - b1), nb2 = bb + at * (sb - b2);
                    A[0 * NV + (int)(ipk[g][0] & 0xFFFFu)] = na0;
                    A[1 * NV + (int)(ipk[g][1] & 0xFFFFu)] = na1;
                    A[2 * NV + (int)(ipk[g][2] & 0xFFFFu)] = na2;
                    A[0 * NV + (int)(ipk[g][0] >> 16)]     = nb0;
                    A[1 * NV + (int)(ipk[g][1] >> 16)]     = nb1;
                    A[2 * NV + (int)(ipk[g][2] >> 16)]     = nb2;
                }
                __syncthreads();
            }
        }

        // ---------- posterior + hard decision (coalesced c2v reads) ----------
#pragma unroll
        for (int k = 0; k < VPT; k++) {
            int v = tid + k * TPB;
            float post = llrv[k] + (Bm[v] + Bm[NV + v] + Bm[2 * NV + v]);
            size_t idx = (size_t)cw * NV + v;
            if (mode) {
                // out = [decoded_bits (as f32 0/1) | posterior], each [B,N]
                out_f[idx] = (post < 0.0f) ? 1.0f : 0.0f;
                out_f[(size_t)B * NV + idx] = post;
            } else {
                out_i[idx] = (post < 0.0f) ? 1 : 0;
            }
        }
        __syncthreads();   // protect smem before next codeword reuses it
    }
}

extern "C" void kernel_launch(void* const* d_in, const int* in_sizes, int n_in,
                              void* d_out, int out_size) {
    // metadata order: llr [B,N] f32, edge_v [E] i32, edge_c [E] i32 (implicit),
    // beta [T] f32, alpha [T] f32
    const float* llr    = (const float*)d_in[0];
    const int*   edge_v = (const int*)  d_in[1];
    const float* beta   = (const float*)d_in[3];
    const float* alpha  = (const float*)d_in[4];

    int B = in_sizes[0] / NV;
    int T = in_sizes[3];
    int mode = (out_size >= 2 * B * NV) ? 1 : 0;

    cudaFuncSetAttribute((const void*)bp_kernel,
                         cudaFuncAttributeMaxDynamicSharedMemorySize, SMEM_BYTES);
    bp_kernel<<<B, TPB, SMEM_BYTES>>>(llr, edge_v, beta, alpha,
                                      (float*)d_out, (int*)d_out, B, T, mode);
}

// round 16
// speedup vs baseline: 1.2403x; 1.2403x over previous
#include <cuda_runtime.h>

// Neural 2D min-sum LDPC decoder, (3,6)-regular layered graph.
// FINAL (= R10, measured best 161.8us): one CTA per codeword (TPB=1024, 96KB
// smem, 1 CTA/SM). Edge state msg[l*NV+v] smem-resident for all T iterations;
// in-place check/variable updates (per layer each variable is in exactly one
// check). Check c, layer l owns edges e = l*NV + 2c + {0,1} (edge_c = i>>1).
//
// Validated design laws from this session's measurements:
//  - binding resource: L1 shared wavefronts; 2 random smem ops/edge/iter is the
//    floor; conflict degree ~3.4 is intrinsic to the random permutation.
//  - var phase MUST be strided scalar 4B (coalesced); vector/paired layouts
//    double conflict phases (R5/R6).
//  - 1-deep check-phase software pipeline is optimal (R10); deeper batching is
//    neutral-negative (R13); LSU queue already full.
//  - 1 CTA x 1024 beats 2 CTA x 512 (R8/R14); store-side randomness is no
//    cheaper than load-side (R15).

#define NV 8192
#define MC 4096
#define NL 3
#define TPB 1024
#define VPT (NV / TPB)    // 8 strided variables per thread
#define CPT (MC / TPB)    // 4 checks per thread (strided)
#define SMEM_BYTES (NL * NV * 4)

// Multiset 2-min min-sum core on sign-magnitude bits; exactly reproduces the
// reference min1/min2/argmin + sign-product semantics (incl. ties and zeros).
// (validated rel_err==0.0 in R5-R15 benches)
__device__ __forceinline__ void minsum6(const unsigned u[6], float bt, unsigned res[6])
{
    unsigned a0 = u[0] & 0x7fffffffu, a1 = u[1] & 0x7fffffffu;
    unsigned a2 = u[2] & 0x7fffffffu, a3 = u[3] & 0x7fffffffu;
    unsigned a4 = u[4] & 0x7fffffffu, a5 = u[5] & 0x7fffffffu;
    unsigned xs = (u[0] ^ u[1]) ^ (u[2] ^ u[3]) ^ (u[4] ^ u[5]);

    // nonnegative float bits order as unsigned ints
    unsigned lo01 = min(a0, a1), hi01 = max(a0, a1);
    unsigned lo23 = min(a2, a3), hi23 = max(a2, a3);
    unsigned lo45 = min(a4, a5), hi45 = max(a4, a5);
    unsigned m1a  = min(lo01, lo23);
    unsigned m2a  = min(max(lo01, lo23), min(hi01, hi23));
    unsigned m1   = min(m1a, lo45);
    unsigned m2   = min(max(m1a, lo45), min(m2a, hi45));
    m2 = (m1 == 0u) ? 0u : m2;   // exact zero => sign product 0 => all c2v = 0

    unsigned b1 = __float_as_uint(bt * __uint_as_float(m1));
    unsigned b2 = __float_as_uint(bt * __uint_as_float(m2));

    unsigned as[6] = {a0, a1, a2, a3, a4, a5};
#pragma unroll
    for (int p = 0; p < 6; p++) {
        unsigned mag = (as[p] == m1) ? b2 : b1;          // ties => b1==b2
        res[p] = mag ^ ((xs ^ u[p]) & 0x80000000u);
    }
}

__global__ __launch_bounds__(TPB, 1)
void bp_kernel(const float* __restrict__ llr,
               const int*   __restrict__ edge_v,
               const float* __restrict__ beta,
               const float* __restrict__ alpha,
               float* __restrict__ out_f,
               int*   __restrict__ out_i,
               int B, int T, int mode)
{
    extern __shared__ float msg[];   // [NL*NV]

    const int tid = threadIdx.x;

    // Register-resident check->var table (graph fixed across codewords/iters).
    unsigned pk[CPT][NL];
#pragma unroll
    for (int k = 0; k < CPT; k++) {
        int c = tid + k * TPB;
#pragma unroll
        for (int l = 0; l < NL; l++) {
            unsigned v0 = (unsigned)edge_v[l * NV + 2 * c];
            unsigned v1 = (unsigned)edge_v[l * NV + 2 * c + 1];
            pk[k][l] = v0 | (v1 << 16);
        }
    }

    for (int cw = blockIdx.x; cw < B; cw += gridDim.x) {
        // Channel LLRs: strided, coalesced, register-resident for the codeword.
        float llrv[VPT];
#pragma unroll
        for (int k = 0; k < VPT; k++)
            llrv[k] = llr[(size_t)cw * NV + tid + k * TPB];

        // v2c init = llr at each edge (coalesced scalar stores).
#pragma unroll
        for (int l = 0; l < NL; l++)
#pragma unroll
            for (int k = 0; k < VPT; k++)
                msg[l * NV + tid + k * TPB] = llrv[k];
        __syncthreads();

        for (int t = 0; t < T; t++) {
            float bt = __ldg(beta + t);
            float at = __ldg(alpha + t);

            // ---------- check phase: v2c -> c2v, software-pipelined ----------
            unsigned ucur[6], unxt[6];
#pragma unroll
            for (int l = 0; l < NL; l++) {
                ucur[2 * l]     = __float_as_uint(msg[l * NV + (int)(pk[0][l] & 0xFFFFu)]);
                ucur[2 * l + 1] = __float_as_uint(msg[l * NV + (int)(pk[0][l] >> 16)]);
            }
#pragma unroll
            for (int k = 0; k < CPT; k++) {
                // Prefetch next check's messages BEFORE storing this check's:
                // no alias possible (checks own disjoint variables per layer).
                if (k + 1 < CPT) {
#pragma unroll
                    for (int l = 0; l < NL; l++) {
                        unxt[2 * l]     = __float_as_uint(msg[l * NV + (int)(pk[k + 1][l] & 0xFFFFu)]);
                        unxt[2 * l + 1] = __float_as_uint(msg[l * NV + (int)(pk[k + 1][l] >> 16)]);
                    }
                }
                unsigned r[6];
                minsum6(ucur, bt, r);     // overlaps with unxt loads in flight
#pragma unroll
                for (int l = 0; l < NL; l++) {
                    msg[l * NV + (int)(pk[k][l] & 0xFFFFu)] = __uint_as_float(r[2 * l]);
                    msg[l * NV + (int)(pk[k][l] >> 16)]     = __uint_as_float(r[2 * l + 1]);
                }
                if (k + 1 < CPT) {
#pragma unroll
                    for (int p = 0; p < 6; p++) ucur[p] = unxt[p];
                }
            }
            __syncthreads();

            // ---------- variable phase: c2v -> v2c, 2-stride batches ----------
            if (t + 1 < T) {
#pragma unroll
                for (int k = 0; k < VPT; k += 2) {
                    int va = tid + k * TPB;          // coalesced, conflict-free
                    int vb = tid + (k + 1) * TPB;
                    float a0 = msg[va], a1 = msg[NV + va], a2 = msg[2 * NV + va];
                    float b0 = msg[vb], b1 = msg[NV + vb], b2 = msg[2 * NV + vb];
                    float sa = a0 + a1 + a2, ba = llrv[k];
                    float sb = b0 + b1 + b2, bb = llrv[k + 1];
                    msg[va]          = ba + at * (sa - a0);
                    msg[NV + va]     = ba + at * (sa - a1);
                    msg[2 * NV + va] = ba + at * (sa - a2);
                    msg[vb]          = bb + at * (sb - b0);
                    msg[NV + vb]     = bb + at * (sb - b1);
                    msg[2 * NV + vb] = bb + at * (sb - b2);
                }
                __syncthreads();
            }
        }

        // ---------- posterior + hard decision ----------
#pragma unroll
        for (int k = 0; k < VPT; k++) {
            int v = tid + k * TPB;
            float post = llrv[k] + (msg[v] + msg[NV + v] + msg[2 * NV + v]);
            size_t idx = (size_t)cw * NV + v;
            if (mode) {
                // out = [decoded_bits (as f32 0/1) | posterior], each [B,N]
                out_f[idx] = (post < 0.0f) ? 1.0f : 0.0f;
                out_f[(size_t)B * NV + idx] = post;
            } else {
                out_i[idx] = (post < 0.0f) ? 1 : 0;
            }
        }
        __syncthreads();   // protect msg before next codeword reuses it
    }
}

extern "C" void kernel_launch(void* const* d_in, const int* in_sizes, int n_in,
                              void* d_out, int out_size) {
    // metadata order: llr [B,N] f32, edge_v [E] i32, edge_c [E] i32 (implicit),
    // beta [T] f32, alpha [T] f32
    const float* llr    = (const float*)d_in[0];
    const int*   edge_v = (const int*)  d_in[1];
    const float* beta   = (const float*)d_in[3];
    const float* alpha  = (const float*)d_in[4];

    int B = in_sizes[0] / NV;
    int T = in_sizes[3];
    int mode = (out_size >= 2 * B * NV) ? 1 : 0;

    cudaFuncSetAttribute((const void*)bp_kernel,
                         cudaFuncAttributeMaxDynamicSharedMemorySize, SMEM_BYTES);
    bp_kernel<<<B, TPB, SMEM_BYTES>>>(llr, edge_v, beta, alpha,
                                      (float*)d_out, (int*)d_out, B, T, mode);
}